// round 12
// baseline (speedup 1.0000x reference)
#include <cuda_runtime.h>
#include <cuda_bf16.h>
#include <cstdint>

// Problem constants
#define BATCH      32768
#define INPUT_DIM  256
#define NNEUR      128
#define NDEG       8                     // D+1 coefficients per input dim
#define NFEAT      (INPUT_DIM * NDEG)    // 2048
#define NG4        (BATCH / 4)           // 8192 groups of 4 rows

#define GRID_MAIN  304                   // 152 SMs x 2 resident blocks
#define THREADS    256
#define NWARPS     (GRID_MAIN * THREADS / 32)   // 2432

// Transformed + packed coefficient table (8 KB), produced by kan_prep.
// Granule linear index m in [0,512): m = (q*4 + gj)*32 + lane.
// Lane owns inputs i = lane*8 .. lane*8+7 (pairs p = lane*4+q).
// Granule gj of pair p holds coefficients (c_{2gj}, c_{2gj+1}) for both
// inputs of the pair: [ c_{2gj}(i0), c_{2gj}(i1), c_{2gj+1}(i0), c_{2gj+1}(i1) ].
// Coefficient order c_0..c_7 = e0,e1,e2,e3,o0,o1,o2,o3 (even/odd Horner).
__device__ float g_pack[NFEAT];
// Per-prep-block partial sums of e0 (prep block b covers inputs 2b, 2b+1).
// Lane's e0 constant = sum of g_e0h[4*lane .. 4*lane+3].
__device__ float g_e0h[128];

// ---------------------------------------------------------------------------
// packed f32x2 helpers (sm_103a FFMA2 path — only reachable via PTX)
// ---------------------------------------------------------------------------
__device__ __forceinline__ float2 ffma2(float2 a, float2 b, float2 c) {
    float2 d;
    asm("fma.rn.f32x2 %0, %1, %2, %3;"
        : "=l"(reinterpret_cast<unsigned long long&>(d))
        : "l"(reinterpret_cast<unsigned long long&>(a)),
          "l"(reinterpret_cast<unsigned long long&>(b)),
          "l"(reinterpret_cast<unsigned long long&>(c)));
    return d;
}
__device__ __forceinline__ float2 fmul2(float2 a, float2 b) {
    float2 d;
    asm("mul.rn.f32x2 %0, %1, %2;"
        : "=l"(reinterpret_cast<unsigned long long&>(d))
        : "l"(reinterpret_cast<unsigned long long&>(a)),
          "l"(reinterpret_cast<unsigned long long&>(b)));
    return d;
}

// 256-bit x-load with L2 evict_last (ptxas requires .v4.b64 for this policy;
// conveniently this also halves the x-load instruction count). Loads 32
// contiguous bytes = 8 floats, returned as 4 packed float2.
// p must be 32-byte aligned.
__device__ __forceinline__ void ldg256_L2last(const void* p, float2 xp[4]) {
    unsigned long long r0, r1, r2, r3;
    asm("ld.global.nc.L2::evict_last.v4.b64 {%0, %1, %2, %3}, [%4];"
        : "=l"(r0), "=l"(r1), "=l"(r2), "=l"(r3) : "l"(p));
    xp[0] = reinterpret_cast<float2&>(r0);
    xp[1] = reinterpret_cast<float2&>(r1);
    xp[2] = reinterpret_cast<float2&>(r2);
    xp[3] = reinterpret_cast<float2&>(r3);
}

// ---------------------------------------------------------------------------
// Prep kernel: C[f] = sum_n coeffs[n][f]; convert Chebyshev T_0..T_7 per
// input to even/odd y-Horner (y=x^2) coeffs; scatter into g_pack / g_e0h.
// grid = 128 blocks x 256 threads; block handles 16 features = 2 inputs.
// ---------------------------------------------------------------------------
__global__ void kan_prep(const float* __restrict__ coeffs) {
    __shared__ float sh[16][16];
    __shared__ float cs[16];
    __shared__ float se0[2];
    const int t  = threadIdx.x;
    const int fl = t & 15;
    const int g  = t >> 4;
    const int f  = blockIdx.x * 16 + fl;

    float s = 0.0f;
#pragma unroll
    for (int n = 0; n < 8; n++)
        s += coeffs[(g * 8 + n) * NFEAT + f];
    sh[g][fl] = s;
    __syncthreads();

    if (t < 16) {
        float c = 0.0f;
#pragma unroll
        for (int gg = 0; gg < 16; gg++) c += sh[gg][t];
        cs[t] = c;
    }
    __syncthreads();

    if (t < 2) {
        const int i = blockIdx.x * 2 + t;   // global input index
        float C[8];
#pragma unroll
        for (int d = 0; d < 8; d++) C[d] = cs[t * 8 + d];

        // T0=1; T1=x; T2=2y-1; T3=x(4y-3); T4=8y^2-8y+1; T5=x(16y^2-20y+5)
        // T6=32y^3-48y^2+18y-1; T7=x(64y^3-112y^2+56y-7)   (y = x^2)
        float cf[8];
        cf[0] = C[0] - C[2] + C[4] - C[6];               // e0
        cf[1] = 2.f*C[2] - 8.f*C[4] + 18.f*C[6];         // e1
        cf[2] = 8.f*C[4] - 48.f*C[6];                    // e2
        cf[3] = 32.f*C[6];                               // e3
        cf[4] = C[1] - 3.f*C[3] + 5.f*C[5] - 7.f*C[7];   // o0
        cf[5] = 4.f*C[3] - 20.f*C[5] + 56.f*C[7];        // o1
        cf[6] = 16.f*C[5] - 112.f*C[7];                  // o2
        cf[7] = 64.f*C[7];                               // o3

        const int p    = i >> 1;       // pair index
        const int lane = p >> 2;       // owning lane
        const int q    = p & 3;        // pair-within-lane
        const int e    = i & 1;        // element within pair
#pragma unroll
        for (int j = 0; j < 8; j++) {
            const int gj = j >> 1;
            g_pack[((q * 4 + gj) * 32 + lane) * 4 + (j & 1) * 2 + e] = cf[j];
        }
        se0[t] = cf[0];
    }
    __syncthreads();
    if (t == 0) g_e0h[blockIdx.x] = se0[0] + se0[1];
}

// ---------------------------------------------------------------------------
// Main kernel (round-10 structure, best measured; delta: x loads are
// 256-bit with L2::evict_last). Persistent, 304 blocks x 8 warps; each warp
// grid-strides over 4-row groups with 4 independent 256-bit loads in
// flight. Coefficients in registers; e0 folded into per-lane constant E0.
// ---------------------------------------------------------------------------
__global__ __launch_bounds__(THREADS, 2)
void kan_main(const float* __restrict__ x, float* __restrict__ out) {
    const int lane   = threadIdx.x & 31;
    const int w      = threadIdx.x >> 5;
    const int warpId = blockIdx.x * (THREADS / 32) + w;

    // Coefficient table: 16 coalesced LDG.128 of the 8 KB L2-resident table.
    const float4* __restrict__ cp = reinterpret_cast<const float4*>(g_pack);
    float4 v[16];
#pragma unroll
    for (int m = 0; m < 16; m++) v[m] = cp[m * 32 + lane];
    const float E0 = g_e0h[4 * lane] + g_e0h[4 * lane + 1]
                   + g_e0h[4 * lane + 2] + g_e0h[4 * lane + 3];

    const char* __restrict__ xb = reinterpret_cast<const char*>(x);

    for (int grp = warpId; grp < NG4; grp += NWARPS) {
        // 4 independent 256-bit loads (one per row), L2 evict_last.
        // Lane slice of row r: 32 bytes at grp*4096 + r*1024 + lane*32.
        const char* gb = xb + (size_t)grp * 4096 + lane * 32;
        float2 xp[4][4];
#pragma unroll
        for (int r = 0; r < 4; r++)
            ldg256_L2last(gb + r * 1024, xp[r]);

#pragma unroll
        for (int r = 0; r < 4; r++) {
            float2 acc = make_float2(E0, 0.0f);
#pragma unroll
            for (int q = 0; q < 4; q++) {
                const float2 X = xp[r][q];
                const float2 Y = fmul2(X, X);
                const float4 g0 = v[q * 4 + 0];   // (e0, e1) — e0 folded into E0
                const float4 g1 = v[q * 4 + 1];   // (e2, e3)
                const float4 g2 = v[q * 4 + 2];   // (o0, o1)
                const float4 g3 = v[q * 4 + 3];   // (o2, o3)
                const float2 e1 = make_float2(g0.z, g0.w);
                const float2 e2 = make_float2(g1.x, g1.y), e3 = make_float2(g1.z, g1.w);
                const float2 o0 = make_float2(g2.x, g2.y), o1 = make_float2(g2.z, g2.w);
                const float2 o2 = make_float2(g3.x, g3.y), o3 = make_float2(g3.z, g3.w);

                // even (minus e0): Y * (e1 + Y*(e2 + Y*e3))
                float2 ev = ffma2(e3, Y, e2);
                ev = ffma2(ev, Y, e1);
                acc = ffma2(ev, Y, acc);
                // odd: X * (o0 + Y*(o1 + Y*(o2 + Y*o3)))
                float2 od = ffma2(o3, Y, o2);
                od = ffma2(od, Y, o1);
                od = ffma2(od, Y, o0);
                acc = ffma2(od, X, acc);
            }
            float s = acc.x + acc.y;
#pragma unroll
            for (int off = 16; off; off >>= 1)
                s += __shfl_xor_sync(0xffffffffu, s, off);
            if (lane == 0) out[grp * 4 + r] = s;
        }
    }
}

// ---------------------------------------------------------------------------
extern "C" void kernel_launch(void* const* d_in, const int* in_sizes, int n_in,
                              void* d_out, int out_size) {
    const float* x      = (const float*)d_in[0];   // [32768, 256]
    const float* coeffs = (const float*)d_in[1];   // [128, 2048]
    float* out          = (float*)d_out;           // [32768, 1]
    (void)in_sizes; (void)n_in; (void)out_size;

    kan_prep<<<NFEAT / 16, 256>>>(coeffs);
    kan_main<<<GRID_MAIN, THREADS>>>(x, out);
}

// round 13
// speedup vs baseline: 1.0029x; 1.0029x over previous
#include <cuda_runtime.h>
#include <cuda_bf16.h>
#include <cstdint>

// Problem constants
#define BATCH      32768
#define INPUT_DIM  256
#define NNEUR      128
#define NDEG       8                     // D+1 coefficients per input dim
#define NFEAT      (INPUT_DIM * NDEG)    // 2048
#define NG4        (BATCH / 4)           // 8192 groups of 4 rows

#define GRID_MAIN  304                   // 152 SMs x 2 resident blocks
#define THREADS    256
#define NWARPS     (GRID_MAIN * THREADS / 32)   // 2432

// Transformed + packed coefficient table (8 KB), produced by kan_prep.
// Granule linear index m in [0,512): m = (q*4 + gj)*32 + lane.
// Lane owns inputs i = lane*8 .. lane*8+7 (pairs p = lane*4+q).
// Granule gj of pair p holds coefficients (c_{2gj}, c_{2gj+1}) for both
// inputs of the pair: [ c_{2gj}(i0), c_{2gj}(i1), c_{2gj+1}(i0), c_{2gj+1}(i1) ].
// Coefficient order c_0..c_7 = e0,e1,e2,e3,o0,o1,o2,o3 (even/odd Horner).
__device__ float g_pack[NFEAT];
// Per-prep-block partial sums of e0 (prep block b covers inputs 2b, 2b+1).
// Lane's e0 constant = sum of g_e0h[4*lane .. 4*lane+3].
__device__ float g_e0h[128];

// ---------------------------------------------------------------------------
// packed f32x2 helpers (sm_103a FFMA2 path — only reachable via PTX)
// ---------------------------------------------------------------------------
__device__ __forceinline__ float2 ffma2(float2 a, float2 b, float2 c) {
    float2 d;
    asm("fma.rn.f32x2 %0, %1, %2, %3;"
        : "=l"(reinterpret_cast<unsigned long long&>(d))
        : "l"(reinterpret_cast<unsigned long long&>(a)),
          "l"(reinterpret_cast<unsigned long long&>(b)),
          "l"(reinterpret_cast<unsigned long long&>(c)));
    return d;
}
__device__ __forceinline__ float2 fmul2(float2 a, float2 b) {
    float2 d;
    asm("mul.rn.f32x2 %0, %1, %2;"
        : "=l"(reinterpret_cast<unsigned long long&>(d))
        : "l"(reinterpret_cast<unsigned long long&>(a)),
          "l"(reinterpret_cast<unsigned long long&>(b)));
    return d;
}

// ---------------------------------------------------------------------------
// Prep kernel: C[f] = sum_n coeffs[n][f]; convert Chebyshev T_0..T_7 per
// input to even/odd y-Horner (y=x^2) coeffs; scatter into g_pack / g_e0h.
// grid = 128 blocks x 256 threads; block handles 16 features = 2 inputs.
// ---------------------------------------------------------------------------
__global__ void kan_prep(const float* __restrict__ coeffs) {
    __shared__ float sh[16][16];
    __shared__ float cs[16];
    __shared__ float se0[2];
    const int t  = threadIdx.x;
    const int fl = t & 15;
    const int g  = t >> 4;
    const int f  = blockIdx.x * 16 + fl;

    float s = 0.0f;
#pragma unroll
    for (int n = 0; n < 8; n++)
        s += coeffs[(g * 8 + n) * NFEAT + f];
    sh[g][fl] = s;
    __syncthreads();

    if (t < 16) {
        float c = 0.0f;
#pragma unroll
        for (int gg = 0; gg < 16; gg++) c += sh[gg][t];
        cs[t] = c;
    }
    __syncthreads();

    if (t < 2) {
        const int i = blockIdx.x * 2 + t;   // global input index
        float C[8];
#pragma unroll
        for (int d = 0; d < 8; d++) C[d] = cs[t * 8 + d];

        // T0=1; T1=x; T2=2y-1; T3=x(4y-3); T4=8y^2-8y+1; T5=x(16y^2-20y+5)
        // T6=32y^3-48y^2+18y-1; T7=x(64y^3-112y^2+56y-7)   (y = x^2)
        float cf[8];
        cf[0] = C[0] - C[2] + C[4] - C[6];               // e0
        cf[1] = 2.f*C[2] - 8.f*C[4] + 18.f*C[6];         // e1
        cf[2] = 8.f*C[4] - 48.f*C[6];                    // e2
        cf[3] = 32.f*C[6];                               // e3
        cf[4] = C[1] - 3.f*C[3] + 5.f*C[5] - 7.f*C[7];   // o0
        cf[5] = 4.f*C[3] - 20.f*C[5] + 56.f*C[7];        // o1
        cf[6] = 16.f*C[5] - 112.f*C[7];                  // o2
        cf[7] = 64.f*C[7];                               // o3

        const int p    = i >> 1;       // pair index
        const int lane = p >> 2;       // owning lane
        const int q    = p & 3;        // pair-within-lane
        const int e    = i & 1;        // element within pair
#pragma unroll
        for (int j = 0; j < 8; j++) {
            const int gj = j >> 1;
            g_pack[((q * 4 + gj) * 32 + lane) * 4 + (j & 1) * 2 + e] = cf[j];
        }
        se0[t] = cf[0];
    }
    __syncthreads();
    if (t == 0) g_e0h[blockIdx.x] = se0[0] + se0[1];
}

// ---------------------------------------------------------------------------
// Main kernel (best measured configuration, rounds 2/10): persistent,
// 304 blocks x 8 warps; each warp grid-strides over 4-row groups with 8
// independent LDG.128 in flight per group. Coefficients live in registers
// for the warp's whole lifetime; e0 folded into a per-lane constant E0.
// Memory-bound at the ~3.1 TB/s serving-rate floor (verified structure-
// independent across LDG / cp.async / TMA / occupancy variants).
// ---------------------------------------------------------------------------
__global__ __launch_bounds__(THREADS, 2)
void kan_main(const float* __restrict__ x, float* __restrict__ out) {
    const int lane   = threadIdx.x & 31;
    const int w      = threadIdx.x >> 5;
    const int warpId = blockIdx.x * (THREADS / 32) + w;

    // Coefficient table: 16 coalesced LDG.128 of the 8 KB L2-resident table.
    const float4* __restrict__ cp = reinterpret_cast<const float4*>(g_pack);
    float4 v[16];
#pragma unroll
    for (int m = 0; m < 16; m++) v[m] = cp[m * 32 + lane];
    const float E0 = g_e0h[4 * lane] + g_e0h[4 * lane + 1]
                   + g_e0h[4 * lane + 2] + g_e0h[4 * lane + 3];

    const float4* __restrict__ xr = reinterpret_cast<const float4*>(x);

    for (int grp = warpId; grp < NG4; grp += NWARPS) {
        // 8 coalesced, independent LDG.128 for 4 rows.
        float4 xa[4], xb[4];
        const int base = grp * 256 + lane * 2;   // group = 4 rows x 64 float4
#pragma unroll
        for (int r = 0; r < 4; r++) {
            xa[r] = xr[base + r * 64];
            xb[r] = xr[base + r * 64 + 1];
        }

#pragma unroll
        for (int r = 0; r < 4; r++) {
            float2 xp[4];
            xp[0] = make_float2(xa[r].x, xa[r].y);
            xp[1] = make_float2(xa[r].z, xa[r].w);
            xp[2] = make_float2(xb[r].x, xb[r].y);
            xp[3] = make_float2(xb[r].z, xb[r].w);

            float2 acc = make_float2(E0, 0.0f);
#pragma unroll
            for (int q = 0; q < 4; q++) {
                const float2 X = xp[q];
                const float2 Y = fmul2(X, X);
                const float4 g0 = v[q * 4 + 0];   // (e0, e1) — e0 folded into E0
                const float4 g1 = v[q * 4 + 1];   // (e2, e3)
                const float4 g2 = v[q * 4 + 2];   // (o0, o1)
                const float4 g3 = v[q * 4 + 3];   // (o2, o3)
                const float2 e1 = make_float2(g0.z, g0.w);
                const float2 e2 = make_float2(g1.x, g1.y), e3 = make_float2(g1.z, g1.w);
                const float2 o0 = make_float2(g2.x, g2.y), o1 = make_float2(g2.z, g2.w);
                const float2 o2 = make_float2(g3.x, g3.y), o3 = make_float2(g3.z, g3.w);

                // even (minus e0): Y * (e1 + Y*(e2 + Y*e3))
                float2 ev = ffma2(e3, Y, e2);
                ev = ffma2(ev, Y, e1);
                acc = ffma2(ev, Y, acc);
                // odd: X * (o0 + Y*(o1 + Y*(o2 + Y*o3)))
                float2 od = ffma2(o3, Y, o2);
                od = ffma2(od, Y, o1);
                od = ffma2(od, Y, o0);
                acc = ffma2(od, X, acc);
            }
            float s = acc.x + acc.y;
#pragma unroll
            for (int off = 16; off; off >>= 1)
                s += __shfl_xor_sync(0xffffffffu, s, off);
            if (lane == 0) out[grp * 4 + r] = s;
        }
    }
}

// ---------------------------------------------------------------------------
extern "C" void kernel_launch(void* const* d_in, const int* in_sizes, int n_in,
                              void* d_out, int out_size) {
    const float* x      = (const float*)d_in[0];   // [32768, 256]
    const float* coeffs = (const float*)d_in[1];   // [128, 2048]
    float* out          = (float*)d_out;           // [32768, 1]
    (void)in_sizes; (void)n_in; (void)out_size;

    kan_prep<<<NFEAT / 16, 256>>>(coeffs);
    kan_main<<<GRID_MAIN, THREADS>>>(x, out);
}

// round 14
// speedup vs baseline: 1.0269x; 1.0239x over previous
#include <cuda_runtime.h>
#include <cuda_bf16.h>
#include <cstdint>

// Problem constants
#define BATCH      32768
#define INPUT_DIM  256
#define NNEUR      128
#define NDEG       8                     // D+1 coefficients per input dim
#define NFEAT      (INPUT_DIM * NDEG)    // 2048
#define NG4        (BATCH / 4)           // 8192 groups of 4 rows

#define GRID_MAIN  304                   // 152 SMs x 2 resident blocks
#define THREADS    256
#define NWARPS     (GRID_MAIN * THREADS / 32)   // 2432

// Transformed + packed coefficient table (8 KB), produced by kan_prep.
// Granule linear index m in [0,512): m = (q*4 + gj)*32 + lane.
// Lane owns inputs i = lane*8 .. lane*8+7 (pairs p = lane*4+q).
// Granule gj of pair p holds coefficients (c_{2gj}, c_{2gj+1}) for both
// inputs of the pair: [ c_{2gj}(i0), c_{2gj}(i1), c_{2gj+1}(i0), c_{2gj+1}(i1) ].
// Coefficient order c_0..c_7 = e0,e1,e2,e3,o0,o1,o2,o3 (even/odd Horner).
__device__ float g_pack[NFEAT];
// Per-prep-block partial sums of e0 (prep block b covers inputs 2b, 2b+1).
// Lane's e0 constant = sum of g_e0h[4*lane .. 4*lane+3].
__device__ float g_e0h[128];

// ---------------------------------------------------------------------------
// packed f32x2 helpers (sm_103a FFMA2 path — only reachable via PTX)
// ---------------------------------------------------------------------------
__device__ __forceinline__ float2 ffma2(float2 a, float2 b, float2 c) {
    float2 d;
    asm("fma.rn.f32x2 %0, %1, %2, %3;"
        : "=l"(reinterpret_cast<unsigned long long&>(d))
        : "l"(reinterpret_cast<unsigned long long&>(a)),
          "l"(reinterpret_cast<unsigned long long&>(b)),
          "l"(reinterpret_cast<unsigned long long&>(c)));
    return d;
}
__device__ __forceinline__ float2 fmul2(float2 a, float2 b) {
    float2 d;
    asm("mul.rn.f32x2 %0, %1, %2;"
        : "=l"(reinterpret_cast<unsigned long long&>(d))
        : "l"(reinterpret_cast<unsigned long long&>(a)),
          "l"(reinterpret_cast<unsigned long long&>(b)));
    return d;
}

// ---------------------------------------------------------------------------
// Prep kernel: C[f] = sum_n coeffs[n][f]; convert Chebyshev T_0..T_7 per
// input to even/odd y-Horner (y=x^2) coeffs; scatter into g_pack / g_e0h.
// grid = 128 blocks x 256 threads; block handles 16 features = 2 inputs.
// ---------------------------------------------------------------------------
__global__ void kan_prep(const float* __restrict__ coeffs) {
    __shared__ float sh[16][16];
    __shared__ float cs[16];
    __shared__ float se0[2];
    const int t  = threadIdx.x;
    const int fl = t & 15;
    const int g  = t >> 4;
    const int f  = blockIdx.x * 16 + fl;

    float s = 0.0f;
#pragma unroll
    for (int n = 0; n < 8; n++)
        s += coeffs[(g * 8 + n) * NFEAT + f];
    sh[g][fl] = s;
    __syncthreads();

    if (t < 16) {
        float c = 0.0f;
#pragma unroll
        for (int gg = 0; gg < 16; gg++) c += sh[gg][t];
        cs[t] = c;
    }
    __syncthreads();

    if (t < 2) {
        const int i = blockIdx.x * 2 + t;   // global input index
        float C[8];
#pragma unroll
        for (int d = 0; d < 8; d++) C[d] = cs[t * 8 + d];

        // T0=1; T1=x; T2=2y-1; T3=x(4y-3); T4=8y^2-8y+1; T5=x(16y^2-20y+5)
        // T6=32y^3-48y^2+18y-1; T7=x(64y^3-112y^2+56y-7)   (y = x^2)
        float cf[8];
        cf[0] = C[0] - C[2] + C[4] - C[6];               // e0
        cf[1] = 2.f*C[2] - 8.f*C[4] + 18.f*C[6];         // e1
        cf[2] = 8.f*C[4] - 48.f*C[6];                    // e2
        cf[3] = 32.f*C[6];                               // e3
        cf[4] = C[1] - 3.f*C[3] + 5.f*C[5] - 7.f*C[7];   // o0
        cf[5] = 4.f*C[3] - 20.f*C[5] + 56.f*C[7];        // o1
        cf[6] = 16.f*C[5] - 112.f*C[7];                  // o2
        cf[7] = 64.f*C[7];                               // o3

        const int p    = i >> 1;       // pair index
        const int lane = p >> 2;       // owning lane
        const int q    = p & 3;        // pair-within-lane
        const int e    = i & 1;        // element within pair
#pragma unroll
        for (int j = 0; j < 8; j++) {
            const int gj = j >> 1;
            g_pack[((q * 4 + gj) * 32 + lane) * 4 + (j & 1) * 2 + e] = cf[j];
        }
        se0[t] = cf[0];
    }
    __syncthreads();
    if (t == 0) g_e0h[blockIdx.x] = se0[0] + se0[1];
}

// ---------------------------------------------------------------------------
// Main kernel (best measured configuration; delta vs round 13: 4-row shared
// reduction tree, 14 SHFL instead of 20). Persistent, 304 blocks x 8 warps;
// each warp grid-strides over 4-row groups with 8 independent LDG.128 in
// flight per group. Coefficients in registers; e0 folded into E0.
// ---------------------------------------------------------------------------
__global__ __launch_bounds__(THREADS, 2)
void kan_main(const float* __restrict__ x, float* __restrict__ out) {
    const int lane   = threadIdx.x & 31;
    const int w      = threadIdx.x >> 5;
    const int warpId = blockIdx.x * (THREADS / 32) + w;

    // Coefficient table: 16 coalesced LDG.128 of the 8 KB L2-resident table.
    const float4* __restrict__ cp = reinterpret_cast<const float4*>(g_pack);
    float4 v[16];
#pragma unroll
    for (int m = 0; m < 16; m++) v[m] = cp[m * 32 + lane];
    const float E0 = g_e0h[4 * lane] + g_e0h[4 * lane + 1]
                   + g_e0h[4 * lane + 2] + g_e0h[4 * lane + 3];

    const float4* __restrict__ xr = reinterpret_cast<const float4*>(x);

    for (int grp = warpId; grp < NG4; grp += NWARPS) {
        // 8 coalesced, independent LDG.128 for 4 rows.
        float4 xa[4], xb[4];
        const int base = grp * 256 + lane * 2;   // group = 4 rows x 64 float4
#pragma unroll
        for (int r = 0; r < 4; r++) {
            xa[r] = xr[base + r * 64];
            xb[r] = xr[base + r * 64 + 1];
        }

        float s[4];
#pragma unroll
        for (int r = 0; r < 4; r++) {
            float2 xp[4];
            xp[0] = make_float2(xa[r].x, xa[r].y);
            xp[1] = make_float2(xa[r].z, xa[r].w);
            xp[2] = make_float2(xb[r].x, xb[r].y);
            xp[3] = make_float2(xb[r].z, xb[r].w);

            float2 acc = make_float2(E0, 0.0f);
#pragma unroll
            for (int q = 0; q < 4; q++) {
                const float2 X = xp[q];
                const float2 Y = fmul2(X, X);
                const float4 g0 = v[q * 4 + 0];   // (e0, e1) — e0 folded into E0
                const float4 g1 = v[q * 4 + 1];   // (e2, e3)
                const float4 g2 = v[q * 4 + 2];   // (o0, o1)
                const float4 g3 = v[q * 4 + 3];   // (o2, o3)
                const float2 e1 = make_float2(g0.z, g0.w);
                const float2 e2 = make_float2(g1.x, g1.y), e3 = make_float2(g1.z, g1.w);
                const float2 o0 = make_float2(g2.x, g2.y), o1 = make_float2(g2.z, g2.w);
                const float2 o2 = make_float2(g3.x, g3.y), o3 = make_float2(g3.z, g3.w);

                // even (minus e0): Y * (e1 + Y*(e2 + Y*e3))
                float2 ev = ffma2(e3, Y, e2);
                ev = ffma2(ev, Y, e1);
                acc = ffma2(ev, Y, acc);
                // odd: X * (o0 + Y*(o1 + Y*(o2 + Y*o3)))
                float2 od = ffma2(o3, Y, o2);
                od = ffma2(od, Y, o1);
                od = ffma2(od, Y, o0);
                acc = ffma2(od, X, acc);
            }
            s[r] = acc.x + acc.y;
        }

        // Shared reduction tree: xor 16/8/4 reduces each row within its
        // lane-mod-4 class (12 SHFL)...
#pragma unroll
        for (int off = 16; off >= 4; off >>= 1) {
#pragma unroll
            for (int r = 0; r < 4; r++)
                s[r] += __shfl_xor_sync(0xffffffffu, s[r], off);
        }
        // ...then lane l takes row (l>>2)&3 (two predicated selects, no
        // dynamic indexing) and xor 1/2 folds the four classes (2 SHFL).
        const float pa = (lane & 8) ? s[2] : s[0];
        const float pb = (lane & 8) ? s[3] : s[1];
        float u = (lane & 4) ? pb : pa;
        u += __shfl_xor_sync(0xffffffffu, u, 1);
        u += __shfl_xor_sync(0xffffffffu, u, 2);
        // Rows 0..3 finished at lanes 0, 4, 8, 12.
        if (lane < 16 && (lane & 3) == 0)
            out[grp * 4 + (lane >> 2)] = u;
    }
}

// ---------------------------------------------------------------------------
extern "C" void kernel_launch(void* const* d_in, const int* in_sizes, int n_in,
                              void* d_out, int out_size) {
    const float* x      = (const float*)d_in[0];   // [32768, 256]
    const float* coeffs = (const float*)d_in[1];   // [128, 2048]
    float* out          = (float*)d_out;           // [32768, 1]
    (void)in_sizes; (void)n_in; (void)out_size;

    kan_prep<<<NFEAT / 16, 256>>>(coeffs);
    kan_main<<<GRID_MAIN, THREADS>>>(x, out);
}